// round 2
// baseline (speedup 1.0000x reference)
#include <cuda_runtime.h>

// VectorQuantizer: N=262144 rows, D=64, K=1024 codes, fp32.
//
// Round 2: bit-exact emulation of the reference's fp32 rounding.
//   Reference: d[n,k] = RN( RN(Sx_n + Se_k) - 2*M_nk ),  M = fp32 gemm,
//              argmin = first index of min.
//   - M_nk emulated as serial ascending-d fp32 FMA chain (Eigen gebp order).
//   - final step: fmaf(-2.f, M, T) == RN(T - 2M) in one rounding (2M exact).
//   - Sx/Se are shift-invariant for the argmin (grid argument) -> any order.
//   - output: o = RN(x + RN(q - x))  (straight-through estimator emulation).
// Deterministic: fixed-order reductions, no atomics, no allocations.

#define VQ_N      262144
#define VQ_D      64
#define VQ_K      1024
#define VQ_CHUNK  128
#define VQ_TPB    256
#define VQ_GRID   (VQ_N / VQ_TPB)   // 1024 blocks

__device__ float g_vq_partial[VQ_GRID];

__global__ void __launch_bounds__(VQ_TPB, 2)
vq_main_kernel(const float* __restrict__ x,
               const float* __restrict__ cb,
               float* __restrict__ out,
               int write_q)
{
    __shared__ float s_e[VQ_CHUNK][VQ_D];   // 32 KB codebook chunk
    __shared__ float s_se[VQ_CHUNK];        // ||e||^2 per code (fp32)
    __shared__ float s_red[VQ_TPB];

    const int tid = threadIdx.x;
    const int row = blockIdx.x * VQ_TPB + tid;

    // ---- x row in registers ----
    float4 xr[VQ_D / 4];
    {
        const float4* xp = reinterpret_cast<const float4*>(x + (size_t)row * VQ_D);
        #pragma unroll
        for (int i = 0; i < VQ_D / 4; i++) xr[i] = xp[i];
    }

    // Sx = sum(x^2) fp32 (order-insensitive for the argmin: shift-invariance)
    float Sx;
    {
        float s = 0.0f;
        #pragma unroll
        for (int i = 0; i < VQ_D / 4; i++) {
            s = fmaf(xr[i].x, xr[i].x, s);
            s = fmaf(xr[i].y, xr[i].y, s);
            s = fmaf(xr[i].z, xr[i].z, s);
            s = fmaf(xr[i].w, xr[i].w, s);
        }
        Sx = s;
    }

    float best = 3.0e38f;
    int   bidx = 0;

    for (int c0 = 0; c0 < VQ_K; c0 += VQ_CHUNK) {
        __syncthreads();
        {
            const float4* src = reinterpret_cast<const float4*>(cb + (size_t)c0 * VQ_D);
            float4*       dst = reinterpret_cast<float4*>(&s_e[0][0]);
            #pragma unroll
            for (int i = 0; i < (VQ_CHUNK * VQ_D / 4) / VQ_TPB; i++)
                dst[tid + i * VQ_TPB] = src[tid + i * VQ_TPB];
        }
        __syncthreads();
        if (tid < VQ_CHUNK) {
            float s = 0.0f;
            #pragma unroll
            for (int d = 0; d < VQ_D; d++) {
                float v = s_e[tid][d];
                s = fmaf(v, v, s);          // Se rounding differences are sub-1e-11: harmless
            }
            s_se[tid] = s;
        }
        __syncthreads();

        // ---- 4 codes at a time; each M is a SERIAL ascending-d FMA chain ----
        #pragma unroll 1
        for (int k = 0; k < VQ_CHUNK; k += 4) {
            const float4* e0 = reinterpret_cast<const float4*>(s_e[k + 0]);
            const float4* e1 = reinterpret_cast<const float4*>(s_e[k + 1]);
            const float4* e2 = reinterpret_cast<const float4*>(s_e[k + 2]);
            const float4* e3 = reinterpret_cast<const float4*>(s_e[k + 3]);
            float a0 = 0.0f, a1 = 0.0f, a2 = 0.0f, a3 = 0.0f;
            #pragma unroll
            for (int i = 0; i < VQ_D / 4; i++) {
                float4 q0 = e0[i], q1 = e1[i], q2 = e2[i], q3 = e3[i];
                float4 xv = xr[i];
                a0 = fmaf(xv.x, q0.x, a0); a0 = fmaf(xv.y, q0.y, a0);
                a0 = fmaf(xv.z, q0.z, a0); a0 = fmaf(xv.w, q0.w, a0);
                a1 = fmaf(xv.x, q1.x, a1); a1 = fmaf(xv.y, q1.y, a1);
                a1 = fmaf(xv.z, q1.z, a1); a1 = fmaf(xv.w, q1.w, a1);
                a2 = fmaf(xv.x, q2.x, a2); a2 = fmaf(xv.y, q2.y, a2);
                a2 = fmaf(xv.z, q2.z, a2); a2 = fmaf(xv.w, q2.w, a2);
                a3 = fmaf(xv.x, q3.x, a3); a3 = fmaf(xv.y, q3.y, a3);
                a3 = fmaf(xv.z, q3.z, a3); a3 = fmaf(xv.w, q3.w, a3);
            }
            // d = RN( RN(Sx + Se) - 2*M ), exactly as the reference rounds it
            float t0 = Sx + s_se[k + 0];
            float t1 = Sx + s_se[k + 1];
            float t2 = Sx + s_se[k + 2];
            float t3 = Sx + s_se[k + 3];
            float d0 = fmaf(-2.0f, a0, t0);
            float d1 = fmaf(-2.0f, a1, t1);
            float d2 = fmaf(-2.0f, a2, t2);
            float d3 = fmaf(-2.0f, a3, t3);
            // first-index min semantics: strict <, ascending k
            if (d0 < best) { best = d0; bidx = c0 + k + 0; }
            if (d1 < best) { best = d1; bidx = c0 + k + 1; }
            if (d2 < best) { best = d2; bidx = c0 + k + 2; }
            if (d3 < best) { best = d3; bidx = c0 + k + 3; }
        }
    }

    // ---- gather, straight-through emulation, loss partial ----
    float rl = 0.0f;
    {
        const float4* qp = reinterpret_cast<const float4*>(cb + (size_t)bidx * VQ_D);
        float4*       op = reinterpret_cast<float4*>(out + (size_t)row * VQ_D);
        #pragma unroll
        for (int i = 0; i < VQ_D / 4; i++) {
            float4 q = qp[i];
            float4 xv = xr[i];
            float rx = q.x - xv.x, ry = q.y - xv.y, rz = q.z - xv.z, rw = q.w - xv.w;
            if (write_q) {
                float4 o;
                o.x = xv.x + rx; o.y = xv.y + ry; o.z = xv.z + rz; o.w = xv.w + rw;
                op[i] = o;
            }
            rl = fmaf(rx, rx, rl); rl = fmaf(ry, ry, rl);
            rl = fmaf(rz, rz, rl); rl = fmaf(rw, rw, rl);
        }
    }

    s_red[tid] = rl;
    __syncthreads();
    #pragma unroll
    for (int s = VQ_TPB / 2; s > 0; s >>= 1) {
        if (tid < s) s_red[tid] += s_red[tid + s];
        __syncthreads();
    }
    if (tid == 0) g_vq_partial[blockIdx.x] = s_red[0];
}

__global__ void vq_loss_kernel(float* __restrict__ out, int out_size)
{
    __shared__ double sd[VQ_TPB];
    const int tid = threadIdx.x;
    double acc = 0.0;
    for (int i = tid; i < VQ_GRID; i += VQ_TPB) acc += (double)g_vq_partial[i];
    sd[tid] = acc;
    __syncthreads();
    #pragma unroll
    for (int s = VQ_TPB / 2; s > 0; s >>= 1) {
        if (tid < s) sd[tid] += sd[tid + s];
        __syncthreads();
    }
    if (tid == 0) {
        double m = sd[0] / (double)((size_t)VQ_N * VQ_D);
        float loss = (float)(1.25 * m);   // q_latent + 0.25*e_latent, both = mean((q-x)^2)
        const long long nq = (long long)VQ_N * VQ_D;
        if (out_size > nq) {
            for (long long i = nq; i < out_size; i++) out[i] = loss;
        } else if (out_size < nq && out_size > 0) {
            out[0] = loss;
        }
    }
}

extern "C" void kernel_launch(void* const* d_in, const int* in_sizes, int n_in,
                              void* d_out, int out_size)
{
    const float* x  = (const float*)d_in[0];
    const float* cb = (const float*)d_in[1];
    float* out = (float*)d_out;

    const long long nq = (long long)VQ_N * VQ_D;
    int write_q = (out_size >= nq) ? 1 : 0;

    vq_main_kernel<<<VQ_GRID, VQ_TPB>>>(x, cb, out, write_q);
    vq_loss_kernel<<<1, VQ_TPB>>>(out, out_size);
}

// round 3
// speedup vs baseline: 1.5671x; 1.5671x over previous
#include <cuda_runtime.h>
#include <cuda_bf16.h>
#include <cstdint>

// VectorQuantizer: N=262144 rows, D=64, K=1024 codes, fp32.
//
// Round 3: tensor-core fast pass (bf16 mma.sync, fp32 accum) + exact fp32
// rescoring of a per-row candidate shortlist.
//   Sweep A: fast scores d~ = Se - 2*M~, per-row min.
//   Sweep B: same gemm, push codes with d~ <= rowmin + MARGIN (27 sigma).
//   Rescore: bit-exact emulation of the reference rounding (identical to the
//   passing R2 kernel): M serial ascending-d fmaf chain, t = Sx + Se,
//   d = fmaf(-2, M, t); argmin strict <, tie -> lowest index.
// Deterministic output (candidate set + min/tie rule are order-invariant).

#define VQ_N       262144
#define VQ_D       64
#define VQ_K       1024
#define VQ_TPB     256
#define VQ_ROWS_PB 128                    // 8 warps x 16 rows
#define VQ_GRID    (VQ_N / VQ_ROWS_PB)   // 2048 blocks
#define VQ_CHUNK   128                   // codes staged per chunk
#define VQ_NCHUNK  (VQ_K / VQ_CHUNK)     // 8
#define VQ_EPAD    72                    // padded bf16 row (144B, 16B-aligned)
#define VQ_SLOTS   16
#define VQ_MARGIN  1e-3f

__device__ float g_vq_partial[VQ_GRID];

__device__ __forceinline__ uint32_t pack_bf16x2(float lo, float hi) {
    __nv_bfloat162 h = __float22bfloat162_rn(make_float2(lo, hi));  // .x = lo bits
    return *reinterpret_cast<uint32_t*>(&h);
}

__device__ __forceinline__ void mma_bf16(float& c0, float& c1, float& c2, float& c3,
                                         uint32_t a0, uint32_t a1, uint32_t a2, uint32_t a3,
                                         uint32_t b0, uint32_t b1) {
    asm volatile(
        "mma.sync.aligned.m16n8k16.row.col.f32.bf16.bf16.f32 "
        "{%0,%1,%2,%3},{%4,%5,%6,%7},{%8,%9},{%0,%1,%2,%3};"
        : "+f"(c0), "+f"(c1), "+f"(c2), "+f"(c3)
        : "r"(a0), "r"(a1), "r"(a2), "r"(a3), "r"(b0), "r"(b1));
}

__device__ __forceinline__ void ldsm_x4(uint32_t& r0, uint32_t& r1, uint32_t& r2, uint32_t& r3,
                                        uint32_t addr) {
    asm volatile("ldmatrix.sync.aligned.m8n8.x4.shared.b16 {%0,%1,%2,%3}, [%4];"
                 : "=r"(r0), "=r"(r1), "=r"(r2), "=r"(r3) : "r"(addr));
}

// Exact reference-rounding distance for (x-row regs, code idx).
__device__ __forceinline__ float exact_dist(const float4* __restrict__ xr, float Sx,
                                            const float* __restrict__ cb,
                                            const float* __restrict__ se, int idx) {
    const float4* e4 = reinterpret_cast<const float4*>(cb + (size_t)idx * VQ_D);
    float m = 0.0f;
    #pragma unroll
    for (int i = 0; i < VQ_D / 4; i++) {
        float4 q = e4[i], xv = xr[i];
        m = fmaf(xv.x, q.x, m); m = fmaf(xv.y, q.y, m);
        m = fmaf(xv.z, q.z, m); m = fmaf(xv.w, q.w, m);
    }
    float t = Sx + se[idx];
    return fmaf(-2.0f, m, t);
}

__global__ void __launch_bounds__(VQ_TPB, 2)
vq_main_kernel(const float* __restrict__ x,
               const float* __restrict__ cb,
               float* __restrict__ out,
               int write_q)
{
    __shared__ __nv_bfloat16 s_e[VQ_CHUNK * VQ_EPAD];   // 18 KB bf16 chunk
    __shared__ float s_Se[VQ_K];                        // exact serial-fmaf norms
    __shared__ float s_rowmin[VQ_ROWS_PB];
    __shared__ int   s_cnt[VQ_ROWS_PB];
    __shared__ int   s_cand[VQ_ROWS_PB][VQ_SLOTS];
    __shared__ int   s_win[VQ_ROWS_PB];
    __shared__ float s_red[VQ_TPB];

    const int tid  = threadIdx.x;
    const int wid  = tid >> 5;
    const int lane = tid & 31;
    const int g    = lane >> 2;         // fragment group (row within 8)
    const int tg   = lane & 3;          // thread-in-group (col pair)
    const int rowbase = blockIdx.x * VQ_ROWS_PB;

    // ---- exact Se (serial ascending fmaf, matches reference emulation) ----
    #pragma unroll
    for (int c = 0; c < VQ_K / VQ_TPB; c++) {
        int code = tid + c * VQ_TPB;
        const float4* e4 = reinterpret_cast<const float4*>(cb + (size_t)code * VQ_D);
        float s = 0.0f;
        #pragma unroll
        for (int i = 0; i < VQ_D / 4; i++) {
            float4 q = e4[i];
            s = fmaf(q.x, q.x, s); s = fmaf(q.y, q.y, s);
            s = fmaf(q.z, q.z, s); s = fmaf(q.w, q.w, s);
        }
        s_Se[code] = s;
    }
    if (tid < VQ_ROWS_PB) s_cnt[tid] = 0;

    // ---- A fragments: this warp's 16 rows (g, g+8), bf16, kept in regs ----
    uint32_t afr[4][4];
    {
        const float* xr0 = x + (size_t)(rowbase + wid * 16 + g) * VQ_D;
        const float* xr1 = xr0 + 8 * VQ_D;
        #pragma unroll
        for (int kt = 0; kt < 4; kt++) {
            int c = kt * 16 + 2 * tg;
            afr[kt][0] = pack_bf16x2(xr0[c],     xr0[c + 1]);
            afr[kt][1] = pack_bf16x2(xr1[c],     xr1[c + 1]);
            afr[kt][2] = pack_bf16x2(xr0[c + 8], xr0[c + 9]);
            afr[kt][3] = pack_bf16x2(xr1[c + 8], xr1[c + 9]);
        }
    }

    // ldmatrix base lane offset within a chunk (code row = lane&7, kseg = lane>>3)
    const uint32_t s_e_base = (uint32_t)__cvta_generic_to_shared(s_e);
    const uint32_t lds_lane = (uint32_t)((lane & 7) * VQ_EPAD * 2 + (lane >> 3) * 16);

    float minr0 = 3.0e38f, minr1 = 3.0e38f;

    // ================= SWEEP A: per-row fast min =================
    for (int ch = 0; ch < VQ_NCHUNK; ch++) {
        const int c0 = ch * VQ_CHUNK;
        __syncthreads();
        {   // stage chunk: thread -> code c0 + tid/2, half (tid&1)*32 elems
            int code = (tid >> 1), half = (tid & 1) * 32;
            const float4* src = reinterpret_cast<const float4*>(
                cb + (size_t)(c0 + code) * VQ_D + half);
            uint32_t* dst = reinterpret_cast<uint32_t*>(
                s_e + code * VQ_EPAD + half);
            #pragma unroll
            for (int i = 0; i < 8; i++) {
                float4 v = src[i];
                dst[2 * i]     = pack_bf16x2(v.x, v.y);
                dst[2 * i + 1] = pack_bf16x2(v.z, v.w);
            }
        }
        __syncthreads();

        #pragma unroll 4
        for (int nt = 0; nt < VQ_CHUNK / 8; nt++) {
            uint32_t base = s_e_base + (uint32_t)(nt * 8 * VQ_EPAD * 2) + lds_lane;
            uint32_t b0, b1, b2, b3, b4, b5, b6, b7;
            ldsm_x4(b0, b1, b2, b3, base);        // kt0 (b0,b1), kt1 (b2,b3)
            ldsm_x4(b4, b5, b6, b7, base + 64);   // kt2, kt3
            float cA0 = 0.f, cA1 = 0.f, cA2 = 0.f, cA3 = 0.f;
            float cB0 = 0.f, cB1 = 0.f, cB2 = 0.f, cB3 = 0.f;
            mma_bf16(cA0, cA1, cA2, cA3, afr[0][0], afr[0][1], afr[0][2], afr[0][3], b0, b1);
            mma_bf16(cB0, cB1, cB2, cB3, afr[2][0], afr[2][1], afr[2][2], afr[2][3], b4, b5);
            mma_bf16(cA0, cA1, cA2, cA3, afr[1][0], afr[1][1], afr[1][2], afr[1][3], b2, b3);
            mma_bf16(cB0, cB1, cB2, cB3, afr[3][0], afr[3][1], afr[3][2], afr[3][3], b6, b7);
            float2 se = *reinterpret_cast<const float2*>(&s_Se[c0 + nt * 8 + 2 * tg]);
            float d0 = fmaf(-2.f, cA0, fmaf(-2.f, cB0, se.x));
            float d1 = fmaf(-2.f, cA1, fmaf(-2.f, cB1, se.y));
            float d2 = fmaf(-2.f, cA2, fmaf(-2.f, cB2, se.x));
            float d3 = fmaf(-2.f, cA3, fmaf(-2.f, cB3, se.y));
            minr0 = fminf(minr0, fminf(d0, d1));
            minr1 = fminf(minr1, fminf(d2, d3));
        }
    }
    // reduce min across the 4 lanes sharing each row
    minr0 = fminf(minr0, __shfl_xor_sync(0xffffffffu, minr0, 1));
    minr0 = fminf(minr0, __shfl_xor_sync(0xffffffffu, minr0, 2));
    minr1 = fminf(minr1, __shfl_xor_sync(0xffffffffu, minr1, 1));
    minr1 = fminf(minr1, __shfl_xor_sync(0xffffffffu, minr1, 2));
    if (tg == 0) {
        s_rowmin[wid * 16 + g]     = minr0;
        s_rowmin[wid * 16 + g + 8] = minr1;
    }
    __syncthreads();

    const float thr0 = s_rowmin[wid * 16 + g]     + VQ_MARGIN;
    const float thr1 = s_rowmin[wid * 16 + g + 8] + VQ_MARGIN;
    const int   r0i  = wid * 16 + g;
    const int   r1i  = r0i + 8;

    // ================= SWEEP B: collect candidates =================
    for (int ch = 0; ch < VQ_NCHUNK; ch++) {
        const int c0 = ch * VQ_CHUNK;
        __syncthreads();
        {
            int code = (tid >> 1), half = (tid & 1) * 32;
            const float4* src = reinterpret_cast<const float4*>(
                cb + (size_t)(c0 + code) * VQ_D + half);
            uint32_t* dst = reinterpret_cast<uint32_t*>(s_e + code * VQ_EPAD + half);
            #pragma unroll
            for (int i = 0; i < 8; i++) {
                float4 v = src[i];
                dst[2 * i]     = pack_bf16x2(v.x, v.y);
                dst[2 * i + 1] = pack_bf16x2(v.z, v.w);
            }
        }
        __syncthreads();

        #pragma unroll 4
        for (int nt = 0; nt < VQ_CHUNK / 8; nt++) {
            uint32_t base = s_e_base + (uint32_t)(nt * 8 * VQ_EPAD * 2) + lds_lane;
            uint32_t b0, b1, b2, b3, b4, b5, b6, b7;
            ldsm_x4(b0, b1, b2, b3, base);
            ldsm_x4(b4, b5, b6, b7, base + 64);
            float cA0 = 0.f, cA1 = 0.f, cA2 = 0.f, cA3 = 0.f;
            float cB0 = 0.f, cB1 = 0.f, cB2 = 0.f, cB3 = 0.f;
            mma_bf16(cA0, cA1, cA2, cA3, afr[0][0], afr[0][1], afr[0][2], afr[0][3], b0, b1);
            mma_bf16(cB0, cB1, cB2, cB3, afr[2][0], afr[2][1], afr[2][2], afr[2][3], b4, b5);
            mma_bf16(cA0, cA1, cA2, cA3, afr[1][0], afr[1][1], afr[1][2], afr[1][3], b2, b3);
            mma_bf16(cB0, cB1, cB2, cB3, afr[3][0], afr[3][1], afr[3][2], afr[3][3], b6, b7);
            float2 se = *reinterpret_cast<const float2*>(&s_Se[c0 + nt * 8 + 2 * tg]);
            float d0 = fmaf(-2.f, cA0, fmaf(-2.f, cB0, se.x));
            float d1 = fmaf(-2.f, cA1, fmaf(-2.f, cB1, se.y));
            float d2 = fmaf(-2.f, cA2, fmaf(-2.f, cB2, se.x));
            float d3 = fmaf(-2.f, cA3, fmaf(-2.f, cB3, se.y));
            int codeb = c0 + nt * 8 + 2 * tg;
            if (d0 <= thr0) { int s = atomicAdd(&s_cnt[r0i], 1); if (s < VQ_SLOTS) s_cand[r0i][s] = codeb; }
            if (d1 <= thr0) { int s = atomicAdd(&s_cnt[r0i], 1); if (s < VQ_SLOTS) s_cand[r0i][s] = codeb + 1; }
            if (d2 <= thr1) { int s = atomicAdd(&s_cnt[r1i], 1); if (s < VQ_SLOTS) s_cand[r1i][s] = codeb; }
            if (d3 <= thr1) { int s = atomicAdd(&s_cnt[r1i], 1); if (s < VQ_SLOTS) s_cand[r1i][s] = codeb + 1; }
        }
    }
    __syncthreads();

    // ================= exact rescore (threads 0..127, one row each) =========
    if (tid < VQ_ROWS_PB) {
        const int row = rowbase + tid;
        float4 xr[VQ_D / 4];
        const float4* xp = reinterpret_cast<const float4*>(x + (size_t)row * VQ_D);
        float Sx = 0.0f;
        #pragma unroll
        for (int i = 0; i < VQ_D / 4; i++) {
            float4 v = xp[i];
            xr[i] = v;
            Sx = fmaf(v.x, v.x, Sx); Sx = fmaf(v.y, v.y, Sx);
            Sx = fmaf(v.z, v.z, Sx); Sx = fmaf(v.w, v.w, Sx);
        }
        int   cnt  = s_cnt[tid];
        float best = 3.0e38f;
        int   bidx = VQ_K;
        if (cnt > VQ_SLOTS || cnt == 0) {
            // overflow fallback (statistically never): full exact scan
            for (int k = 0; k < VQ_K; k++) {
                float d = exact_dist(xr, Sx, cb, s_Se, k);
                if (d < best) { best = d; bidx = k; }
            }
        } else {
            for (int s = 0; s < cnt; s++) {
                int k = s_cand[tid][s];
                float d = exact_dist(xr, Sx, cb, s_Se, k);
                if (d < best || (d == best && k < bidx)) { best = d; bidx = k; }
            }
        }
        s_win[tid] = bidx;
    }
    __syncthreads();

    // ================= output + loss (2 threads per row) ====================
    float rl = 0.0f;
    {
        const int r    = tid >> 1;
        const int half = (tid & 1) * (VQ_D / 2);
        const int row  = rowbase + r;
        const int win  = s_win[r];
        const float4* xp = reinterpret_cast<const float4*>(x + (size_t)row * VQ_D + half);
        const float4* qp = reinterpret_cast<const float4*>(cb + (size_t)win * VQ_D + half);
        float4* op = reinterpret_cast<float4*>(out + (size_t)row * VQ_D + half);
        #pragma unroll
        for (int i = 0; i < VQ_D / 8; i++) {
            float4 q = qp[i], xv = xp[i];
            float rx = q.x - xv.x, ry = q.y - xv.y, rz = q.z - xv.z, rw = q.w - xv.w;
            if (write_q) {
                float4 o; o.x = xv.x + rx; o.y = xv.y + ry; o.z = xv.z + rz; o.w = xv.w + rw;
                op[i] = o;
            }
            rl = fmaf(rx, rx, rl); rl = fmaf(ry, ry, rl);
            rl = fmaf(rz, rz, rl); rl = fmaf(rw, rw, rl);
        }
    }
    s_red[tid] = rl;
    __syncthreads();
    #pragma unroll
    for (int s = VQ_TPB / 2; s > 0; s >>= 1) {
        if (tid < s) s_red[tid] += s_red[tid + s];
        __syncthreads();
    }
    if (tid == 0) g_vq_partial[blockIdx.x] = s_red[0];
}

__global__ void vq_loss_kernel(float* __restrict__ out, int out_size)
{
    __shared__ double sd[VQ_TPB];
    const int tid = threadIdx.x;
    double acc = 0.0;
    for (int i = tid; i < VQ_GRID; i += VQ_TPB) acc += (double)g_vq_partial[i];
    sd[tid] = acc;
    __syncthreads();
    #pragma unroll
    for (int s = VQ_TPB / 2; s > 0; s >>= 1) {
        if (tid < s) sd[tid] += sd[tid + s];
        __syncthreads();
    }
    if (tid == 0) {
        double m = sd[0] / (double)((size_t)VQ_N * VQ_D);
        float loss = (float)(1.25 * m);
        const long long nq = (long long)VQ_N * VQ_D;
        if (out_size > nq) {
            for (long long i = nq; i < out_size; i++) out[i] = loss;
        } else if (out_size < nq && out_size > 0) {
            out[0] = loss;
        }
    }
}

extern "C" void kernel_launch(void* const* d_in, const int* in_sizes, int n_in,
                              void* d_out, int out_size)
{
    const float* x  = (const float*)d_in[0];
    const float* cb = (const float*)d_in[1];
    float* out = (float*)d_out;

    const long long nq = (long long)VQ_N * VQ_D;
    int write_q = (out_size >= nq) ? 1 : 0;

    vq_main_kernel<<<VQ_GRID, VQ_TPB>>>(x, cb, out, write_q);
    vq_loss_kernel<<<1, VQ_TPB>>>(out, out_size);
}